// round 12
// baseline (speedup 1.0000x reference)
#include <cuda_runtime.h>
#include <cuda_bf16.h>
#include <cstdint>

#define N_NODES 20000
#define N_EDGES 320000
#define E_TOT   (N_EDGES + N_NODES)
#define N_GRAPHS 64
#define SPS 68

// ---------------- scratch (device globals; no allocation allowed) ----------
// INVARIANT: g_deg zero at entry (zeroed by k_final tail); g_pool zeroed by k_hist_setup.
__device__ float  g_als1[N_NODES * 8];
__device__ float  g_ald1[N_NODES * 8];
__device__ float4 g_x4[N_NODES];
__device__ float4 g_o14[N_NODES * 16];
__device__ float  g_als2[N_NODES];
__device__ float  g_ald2[N_NODES];
__device__ float4 g_va4[16];
__device__ float4 g_vd4[16];
__device__ __align__(16) __nv_bfloat162 g_t2hi[N_NODES * 32];   // [node][64 k] hi, k-pairs
__device__ __align__(16) __nv_bfloat162 g_t2lo[N_NODES * 32];   // lo
__device__ __align__(16) __nv_bfloat162 g_w2thi[512 * 32];      // W2^T [col][64 k] hi, k-pairs
__device__ __align__(16) __nv_bfloat162 g_w2tlo[512 * 32];      // lo
__device__ int    g_deg[N_NODES];
__device__ int    g_fill[N_NODES];
__device__ int    g_rowstart[N_NODES + 1];
__device__ int    g_csr[E_TOT];
__device__ float  g_pool[N_GRAPHS * 512];
__device__ int    g_cnt[N_GRAPHS];

// ============ K1: hist + cnt + va + pool-zero + W2^T bf16 split ==============
__global__ void k_hist_setup(const int* __restrict__ ei,
                             const float* __restrict__ W2,
                             const float* __restrict__ as2, const float* __restrict__ ad2,
                             const int* __restrict__ batch) {
    int b = blockIdx.x, t = threadIdx.x;
    if (b < 333) {
        int base = b * 1024 + t;
        int dst[4];
#pragma unroll
        for (int j = 0; j < 4; j++) {
            int e = base + j * 256;
            if (e < E_TOT) dst[j] = (e < N_EDGES) ? ei[N_EDGES + e] : (e - N_EDGES);
            else dst[j] = -1;
        }
#pragma unroll
        for (int j = 0; j < 4; j++)
            if (dst[j] >= 0) atomicAdd(&g_deg[dst[j]], 1);
    } else if (b == 333) {
        if (t >= 32 && t < 96) {
            int g = t - 32;
            int lo = 0, hi = N_NODES;
            while (lo < hi) { int m = (lo + hi) >> 1; if (batch[m] < g) lo = m + 1; else hi = m; }
            int s = lo;
            lo = 0; hi = N_NODES;
            int g1 = g + 1;
            while (lo < hi) { int m = (lo + hi) >> 1; if (batch[m] < g1) lo = m + 1; else hi = m; }
            g_cnt[g] = lo - s;
        }
    } else if (b < 342) {
        int warp = (b - 334) * 8 + (t >> 5);
        int lane = t & 31;
        float s = 0.f, d = 0.f;
        for (int c = lane; c < 512; c += 32) {
            float w = W2[warp * 512 + c];
            s += w * as2[c];
            d += w * ad2[c];
        }
        for (int off = 16; off; off >>= 1) {
            s += __shfl_down_sync(0xffffffffu, s, off);
            d += __shfl_down_sync(0xffffffffu, d, off);
        }
        if (lane == 0) { ((float*)g_va4)[warp] = s; ((float*)g_vd4)[warp] = d; }
    } else if (b < 470) {
        int idx = (b - 342) * 256 + t;           // 128*256 == 32768 exactly
        g_pool[idx] = 0.f;
    } else {
        int i = (b - 470) * 256 + t;             // 64*256 == 16384 exactly
        int n = i >> 5, kp = i & 31;
        float w0 = W2[(2 * kp) * 512 + n];
        float w1 = W2[(2 * kp + 1) * 512 + n];
        __nv_bfloat16 h0 = __float2bfloat16(w0), h1 = __float2bfloat16(w1);
        float l0 = w0 - __bfloat162float(h0), l1 = w1 - __bfloat162float(h1);
        __nv_bfloat162 hp; hp.x = h0; hp.y = h1;
        __nv_bfloat162 lp; lp.x = __float2bfloat16(l0); lp.y = __float2bfloat16(l1);
        g_w2thi[n * 32 + kp] = hp;
        g_w2tlo[n * 32 + kp] = lp;
    }
}

// ============ K2: block 0 = shuffle-scan; blocks 1..157 = al1+x4 =============
__global__ void __launch_bounds__(1024)
k_scan_al1(const float* __restrict__ x, const float* __restrict__ W1,
           const float* __restrict__ as1, const float* __restrict__ ad1) {
    int b = blockIdx.x, t = threadIdx.x;
    if (b == 0) {
        __shared__ int sw[32];
        int lane = t & 31, w = t >> 5;
        int v[20];
#pragma unroll
        for (int k = 0; k < 20; k++) {
            int i = k * 1024 + t;
            v[k] = (i < N_NODES) ? g_deg[i] : 0;
        }
        int running = 0;
#pragma unroll
        for (int k = 0; k < 20; k++) {
            int s = v[k];
#pragma unroll
            for (int off = 1; off < 32; off <<= 1) {
                int n = __shfl_up_sync(0xffffffffu, s, off);
                if (lane >= off) s += n;
            }
            if (lane == 31) sw[w] = s;
            __syncthreads();
            if (w == 0) {
                int p = sw[lane];
#pragma unroll
                for (int off = 1; off < 32; off <<= 1) {
                    int n = __shfl_up_sync(0xffffffffu, p, off);
                    if (lane >= off) p += n;
                }
                sw[lane] = p;
            }
            __syncthreads();
            int ex = running + (w ? sw[w - 1] : 0) + s - v[k];
            int i = k * 1024 + t;
            if (i < N_NODES) { g_rowstart[i] = ex; g_fill[i] = ex; }
            running += sw[31];
            __syncthreads();
        }
        if (t == 0) g_rowstart[N_NODES] = running;
    } else {
        __shared__ float sPs[24], sPd[24];
        if (t < 24) {
            int h = t / 3, d = t % 3;
            float ps = 0.f, pd = 0.f;
            for (int c = 0; c < 8; c++) {
                float w = W1[d * 64 + h * 8 + c];
                ps += w * as1[h * 8 + c];
                pd += w * ad1[h * 8 + c];
            }
            sPs[t] = ps;
            sPd[t] = pd;
        }
        __syncthreads();
        int idx = (b - 1) * 1024 + t;
        if (idx < N_NODES * 8) {
            int n = idx >> 3, h = idx & 7;
            float x0 = x[n * 3], x1 = x[n * 3 + 1], x2 = x[n * 3 + 2];
            g_als1[idx] = x0 * sPs[h * 3] + x1 * sPs[h * 3 + 1] + x2 * sPs[h * 3 + 2];
            g_ald1[idx] = x0 * sPd[h * 3] + x1 * sPd[h * 3 + 1] + x2 * sPd[h * 3 + 2];
            if (h == 0) g_x4[n] = make_float4(x0, x1, x2, 0.f);
        }
    }
}

// ============ K3: scatter, 4 edges per thread ================================
__global__ void k_scatter(const int* __restrict__ ei) {
    int base = blockIdx.x * 1024 + threadIdx.x;
    int src[4], dst[4];
#pragma unroll
    for (int j = 0; j < 4; j++) {
        int e = base + j * 256;
        if (e < E_TOT) {
            if (e < N_EDGES) { src[j] = ei[e]; dst[j] = ei[N_EDGES + e]; }
            else             { src[j] = e - N_EDGES; dst[j] = src[j]; }
        } else dst[j] = -1;
    }
#pragma unroll
    for (int j = 0; j < 4; j++) {
        if (dst[j] >= 0) {
            int pos = atomicAdd(&g_fill[dst[j]], 1);
            g_csr[pos] = src[j];
        }
    }
}

// ============ layer-1 aggregate (R6 v3, measured best) =======================
__global__ void k_agg1(const float* __restrict__ W1, const float* __restrict__ b1) {
    int gidx = blockIdx.x * 256 + threadIdx.x;
    int n = gidx >> 4;
    int l = gidx & 15;
    int h = l >> 1, p = l & 1;
    int s0 = g_rowstart[n], s1 = g_rowstart[n + 1];
    int half0 = (s1 - s0 + 1) >> 1;
    int a = p ? (s0 + half0) : s0;
    int bnd = p ? s1 : (s0 + half0);
    float ald = g_ald1[n * 8 + h];
    float wsum = 0.f, xa0 = 0.f, xa1 = 0.f, xa2 = 0.f;
    int i = a;
    for (; i + 2 <= bnd; i += 2) {
        int src0 = g_csr[i], src1 = g_csr[i + 1];
        float e0 = g_als1[src0 * 8 + h] + ald;
        float e1 = g_als1[src1 * 8 + h] + ald;
        float4 xv0 = g_x4[src0];
        float4 xv1 = g_x4[src1];
        e0 = (e0 > 0.f) ? e0 : 0.2f * e0;
        e1 = (e1 > 0.f) ? e1 : 0.2f * e1;
        float w0 = __expf(e0), w1 = __expf(e1);
        wsum += w0 + w1;
        xa0 += w0 * xv0.x + w1 * xv1.x;
        xa1 += w0 * xv0.y + w1 * xv1.y;
        xa2 += w0 * xv0.z + w1 * xv1.z;
    }
    if (i < bnd) {
        int src = g_csr[i];
        float e = g_als1[src * 8 + h] + ald;
        float4 xv = g_x4[src];
        e = (e > 0.f) ? e : 0.2f * e;
        float w = __expf(e);
        wsum += w;
        xa0 += w * xv.x; xa1 += w * xv.y; xa2 += w * xv.z;
    }
    wsum += __shfl_xor_sync(0xffffffffu, wsum, 1);
    xa0  += __shfl_xor_sync(0xffffffffu, xa0, 1);
    xa1  += __shfl_xor_sync(0xffffffffu, xa1, 1);
    xa2  += __shfl_xor_sync(0xffffffffu, xa2, 1);
    float inv = 1.f / wsum;
    xa0 *= inv; xa1 *= inv; xa2 *= inv;
    const float4 w0v = *(const float4*)&W1[4 * l];
    const float4 w1v = *(const float4*)&W1[64 + 4 * l];
    const float4 w2v = *(const float4*)&W1[128 + 4 * l];
    const float4 bv  = *(const float4*)&b1[4 * l];
    float4 o;
    o.x = xa0 * w0v.x + xa1 * w1v.x + xa2 * w2v.x + bv.x;
    o.y = xa0 * w0v.y + xa1 * w1v.y + xa2 * w2v.y + bv.y;
    o.z = xa0 * w0v.z + xa1 * w1v.z + xa2 * w2v.z + bv.z;
    o.w = xa0 * w0v.w + xa1 * w1v.w + xa2 * w2v.w + bv.w;
    o.x = (o.x > 0.f) ? o.x : (__expf(o.x) - 1.f);
    o.y = (o.y > 0.f) ? o.y : (__expf(o.y) - 1.f);
    o.z = (o.z > 0.f) ? o.z : (__expf(o.z) - 1.f);
    o.w = (o.w > 0.f) ? o.w : (__expf(o.w) - 1.f);
    g_o14[n * 16 + l] = o;
    float4 va = g_va4[l], vd = g_vd4[l];
    float ps2 = o.x * va.x + o.y * va.y + o.z * va.z + o.w * va.w;
    float pd2 = o.x * vd.x + o.y * vd.y + o.z * vd.z + o.w * vd.w;
#pragma unroll
    for (int off = 8; off; off >>= 1) {
        ps2 += __shfl_down_sync(0xffffffffu, ps2, off);
        pd2 += __shfl_down_sync(0xffffffffu, pd2, off);
    }
    if (l == 0) { g_als2[n] = ps2; g_ald2[n] = pd2; }
}

// ============ layer-2 aggregate: warp-per-node; emits bf16 hi/lo =============
__global__ void __launch_bounds__(256)
k_agg2() {
    int wid = threadIdx.x >> 5, lane = threadIdx.x & 31;
    int n = blockIdx.x * 8 + wid;
    int q = lane & 15, r = lane >> 4;
    int s0 = g_rowstart[n], s1 = g_rowstart[n + 1];
    float ald = g_ald2[n];
    float wsum = 0.f;
    float4 acc = make_float4(0.f, 0.f, 0.f, 0.f);
    for (int base = s0; base < s1; base += 32) {
        int i = base + lane;
        float w = 0.f;
        int src = 0;
        if (i < s1) {
            src = g_csr[i];
            float e = g_als2[src] + ald;
            e = (e > 0.f) ? e : 0.2f * e;
            w = __expf(e);
        }
        wsum += w;
        int m = (s1 - base < 32) ? (s1 - base) : 32;
        for (int j0 = 0; j0 < m; j0 += 2) {
            int jj = j0 + r;
            float wj = __shfl_sync(0xffffffffu, w, jj & 31);
            int   sj = __shfl_sync(0xffffffffu, src, jj & 31);
            if (jj < m) {
                float4 v = g_o14[sj * 16 + q];
                acc.x += wj * v.x; acc.y += wj * v.y;
                acc.z += wj * v.z; acc.w += wj * v.w;
            }
        }
    }
#pragma unroll
    for (int off = 16; off; off >>= 1)
        wsum += __shfl_xor_sync(0xffffffffu, wsum, off);
    acc.x += __shfl_xor_sync(0xffffffffu, acc.x, 16);
    acc.y += __shfl_xor_sync(0xffffffffu, acc.y, 16);
    acc.z += __shfl_xor_sync(0xffffffffu, acc.z, 16);
    acc.w += __shfl_xor_sync(0xffffffffu, acc.w, 16);
    if (r == 0) {
        float inv = 1.f / wsum;
        acc.x *= inv; acc.y *= inv; acc.z *= inv; acc.w *= inv;
        __nv_bfloat16 hx = __float2bfloat16(acc.x), hy = __float2bfloat16(acc.y);
        __nv_bfloat16 hz = __float2bfloat16(acc.z), hw = __float2bfloat16(acc.w);
        __nv_bfloat162 h01; h01.x = hx; h01.y = hy;
        __nv_bfloat162 h23; h23.x = hz; h23.y = hw;
        __nv_bfloat162 l01, l23;
        l01.x = __float2bfloat16(acc.x - __bfloat162float(hx));
        l01.y = __float2bfloat16(acc.y - __bfloat162float(hy));
        l23.x = __float2bfloat16(acc.z - __bfloat162float(hz));
        l23.y = __float2bfloat16(acc.w - __bfloat162float(hw));
        g_t2hi[n * 32 + q * 2]     = h01;
        g_t2hi[n * 32 + q * 2 + 1] = h23;
        g_t2lo[n * 32 + q * 2]     = l01;
        g_t2lo[n * 32 + q * 2 + 1] = l23;
    }
}

// ============ gemm2 via warp HMMA (m16n8k16 bf16, hi/lo split, 3 passes) =====
// grid 148 x 512; warp owns 32 cols; 1250 tiles of 16 nodes (exact).
#define MMA_BF16(d, A0, A1, A2, A3, B0, B1)                                     \
    asm volatile("mma.sync.aligned.m16n8k16.row.col.f32.bf16.bf16.f32 "         \
                 "{%0,%1,%2,%3}, {%4,%5,%6,%7}, {%8,%9}, {%0,%1,%2,%3};"        \
                 : "+f"((d)[0]), "+f"((d)[1]), "+f"((d)[2]), "+f"((d)[3])       \
                 : "r"(A0), "r"(A1), "r"(A2), "r"(A3), "r"(B0), "r"(B1))

__global__ void __launch_bounds__(512, 1)
k_gemm2_hmma(const float* __restrict__ b2, const int* __restrict__ batch) {
    __shared__ float sstage[16 * 16 * 34];       // per-warp 16x34 padded tiles
    const uint32_t* t2hi = (const uint32_t*)g_t2hi;
    const uint32_t* t2lo = (const uint32_t*)g_t2lo;
    const uint32_t* w2hi = (const uint32_t*)g_w2thi;
    const uint32_t* w2lo = (const uint32_t*)g_w2tlo;
    int tid = threadIdx.x;
    int wid = tid >> 5, lane = tid & 31;
    int g = lane >> 2, tg = lane & 3;
    int cb = wid * 32;
    float b2c = b2[cb + lane];
    float* stg = sstage + wid * (16 * 34);

    // resident B-hi fragments and per-nt base indices
    int bbase[4];
    uint32_t bh[4][4][2];
#pragma unroll
    for (int nt = 0; nt < 4; nt++) {
        int col = cb + nt * 8 + g;
        bbase[nt] = col * 32 + tg;
#pragma unroll
        for (int ks = 0; ks < 4; ks++) {
            bh[nt][ks][0] = w2hi[bbase[nt] + ks * 8];
            bh[nt][ks][1] = w2hi[bbase[nt] + ks * 8 + 4];
        }
    }

    for (int tile = blockIdx.x; tile < N_NODES / 16; tile += (int)gridDim.x) {
        int n0 = tile * 16 + g, n1 = n0 + 8;
        // A fragments (hi+lo), 32 independent 4B loads
        uint32_t ah[4][4], al[4][4];
#pragma unroll
        for (int ks = 0; ks < 4; ks++) {
            int p0 = n0 * 32 + ks * 8 + tg, p1 = n1 * 32 + ks * 8 + tg;
            ah[ks][0] = t2hi[p0];     ah[ks][1] = t2hi[p1];
            ah[ks][2] = t2hi[p0 + 4]; ah[ks][3] = t2hi[p1 + 4];
            al[ks][0] = t2lo[p0];     al[ks][1] = t2lo[p1];
            al[ks][2] = t2lo[p0 + 4]; al[ks][3] = t2lo[p1 + 4];
        }
        int bt = batch[tile * 16 + (lane & 15)];
        float acc[4][4] = {{0.f, 0.f, 0.f, 0.f}, {0.f, 0.f, 0.f, 0.f},
                           {0.f, 0.f, 0.f, 0.f}, {0.f, 0.f, 0.f, 0.f}};
#pragma unroll
        for (int ks = 0; ks < 4; ks++) {
#pragma unroll
            for (int nt = 0; nt < 4; nt++) {
                uint32_t bl0 = w2lo[bbase[nt] + ks * 8];
                uint32_t bl1 = w2lo[bbase[nt] + ks * 8 + 4];
                MMA_BF16(acc[nt], ah[ks][0], ah[ks][1], ah[ks][2], ah[ks][3],
                         bh[nt][ks][0], bh[nt][ks][1]);
                MMA_BF16(acc[nt], ah[ks][0], ah[ks][1], ah[ks][2], ah[ks][3],
                         bl0, bl1);
                MMA_BF16(acc[nt], al[ks][0], al[ks][1], al[ks][2], al[ks][3],
                         bh[nt][ks][0], bh[nt][ks][1]);
            }
        }
        // stage to smem: D[g][2tg+{0,1}] / D[g+8][...] per nt
        __syncwarp();
#pragma unroll
        for (int nt = 0; nt < 4; nt++) {
            int colb = nt * 8 + 2 * tg;
            stg[g * 34 + colb]           = acc[nt][0];
            stg[g * 34 + colb + 1]       = acc[nt][1];
            stg[(g + 8) * 34 + colb]     = acc[nt][2];
            stg[(g + 8) * 34 + colb + 1] = acc[nt][3];
        }
        __syncwarp();
        // run-compressed pooling: lane owns column `lane` (global col cb+lane)
        int bprev = -1;
        float run = 0.f;
#pragma unroll
        for (int r = 0; r < 16; r++) {
            float o = stg[r * 34 + lane] + b2c;
            o = (o > 0.f) ? o : (__expf(o) - 1.f);   // elu
            int bg = __shfl_sync(0xffffffffu, bt, r);
            if (bg != bprev) {
                if (bprev >= 0) atomicAdd(&g_pool[bprev * 512 + cb + lane], run);
                run = 0.f;
                bprev = bg;
            }
            run += o;
        }
        atomicAdd(&g_pool[bprev * 512 + cb + lane], run);
        __syncwarp();
    }
}

// ============ final: block = 8-col slice x all graphs; + deg-zero tail =======
__global__ void k_final(const float* __restrict__ Wo, const float* __restrict__ bo,
                        float* __restrict__ out) {
    int b = blockIdx.x;
    if (b < 64) {
        __shared__ float sP[64 * SPS];
        __shared__ float sW[64 * 8];
        __shared__ float sInv[64];
        int tid = threadIdx.x;           // 512
        int g = tid >> 3, j = tid & 7;
        int c = b * 8 + j;
        if (tid < 64) sInv[tid] = 1.f / fmaxf((float)g_cnt[tid], 1.f);
        __syncthreads();
        int kk0 = (tid & 7) * 8;
        float invg = sInv[g];
        float acc = 0.f;
#pragma unroll 1
        for (int kt = 0; kt < 8; kt++) {
            float4 p0 = *(const float4*)&g_pool[g * 512 + kt * 64 + kk0];
            float4 p1 = *(const float4*)&g_pool[g * 512 + kt * 64 + kk0 + 4];
            p0.x *= invg; p0.y *= invg; p0.z *= invg; p0.w *= invg;
            p1.x *= invg; p1.y *= invg; p1.z *= invg; p1.w *= invg;
            *(float4*)&sP[g * SPS + kk0]     = p0;
            *(float4*)&sP[g * SPS + kk0 + 4] = p1;
            sW[tid] = Wo[(kt * 64 + g) * 512 + c];
            __syncthreads();
#pragma unroll 8
            for (int kk = 0; kk < 64; kk++)
                acc += sP[g * SPS + kk] * sW[kk * 8 + j];
            __syncthreads();
        }
        out[g * 512 + c] = acc + bo[c];
    } else {
        int i = (b - 64) * 512 + threadIdx.x;
        if (i < N_NODES) g_deg[i] = 0;
    }
}

// ---------------- launch -------------------------------------------------------
extern "C" void kernel_launch(void* const* d_in, const int* in_sizes, int n_in,
                              void* d_out, int out_size) {
    const float* x     = (const float*)d_in[0];
    const int*   ei    = (const int*)d_in[1];     // int32 (JAX x64 disabled)
    const int*   batch = (const int*)d_in[2];     // int32
    const float* W1    = (const float*)d_in[3];
    const float* as1   = (const float*)d_in[4];
    const float* ad1   = (const float*)d_in[5];
    const float* b1    = (const float*)d_in[6];
    const float* W2    = (const float*)d_in[7];
    const float* as2   = (const float*)d_in[8];
    const float* ad2   = (const float*)d_in[9];
    const float* b2    = (const float*)d_in[10];
    const float* Wo    = (const float*)d_in[11];
    const float* bo    = (const float*)d_in[12];
    float* out = (float*)d_out;

    k_hist_setup<<<534, 256>>>(ei, W2, as2, ad2, batch);
    k_scan_al1<<<158, 1024>>>(x, W1, as1, ad1);
    k_scatter<<<(E_TOT + 1023) / 1024, 256>>>(ei);
    k_agg1<<<(N_NODES * 16) / 256, 256>>>(W1, b1);
    k_agg2<<<N_NODES / 8, 256>>>();
    k_gemm2_hmma<<<148, 512>>>(b2, batch);
    k_final<<<64 + (N_NODES + 511) / 512, 512>>>(Wo, bo, out);
}

// round 13
// speedup vs baseline: 1.0843x; 1.0843x over previous
#include <cuda_runtime.h>
#include <cuda_bf16.h>
#include <cstdint>

#define N_NODES 20000
#define N_EDGES 320000
#define E_TOT   (N_EDGES + N_NODES)
#define N_GRAPHS 64
#define SPS 68

// ---------------- scratch (device globals; no allocation allowed) ----------
// INVARIANT: g_deg zero at entry (zeroed by k_final tail); g_pool zeroed by k_hist_setup.
__device__ float  g_als1[N_NODES * 8];
__device__ float  g_ald1[N_NODES * 8];
__device__ float4 g_x4[N_NODES];
__device__ float4 g_o14[N_NODES * 16];
__device__ float  g_als2[N_NODES];
__device__ float  g_ald2[N_NODES];
__device__ float4 g_va4[16];
__device__ float4 g_vd4[16];
__device__ __align__(16) __nv_bfloat162 g_t2hi[N_NODES * 32];   // [node][64 k] hi, k-pairs
__device__ __align__(16) __nv_bfloat162 g_t2lo[N_NODES * 32];   // lo
__device__ __align__(16) __nv_bfloat162 g_w2thi[512 * 32];      // W2^T [col][64 k] hi, k-pairs
__device__ __align__(16) __nv_bfloat162 g_w2tlo[512 * 32];      // lo
__device__ int    g_deg[N_NODES];
__device__ int    g_fill[N_NODES];
__device__ int    g_rowstart[N_NODES + 1];
__device__ int    g_csr[E_TOT];
__device__ float  g_pool[N_GRAPHS * 512];
__device__ int    g_cnt[N_GRAPHS];

// ============ K1: hist + cnt + va + pool-zero + W2^T bf16 split ==============
__global__ void k_hist_setup(const int* __restrict__ ei,
                             const float* __restrict__ W2,
                             const float* __restrict__ as2, const float* __restrict__ ad2,
                             const int* __restrict__ batch) {
    int b = blockIdx.x, t = threadIdx.x;
    if (b < 333) {
        int base = b * 1024 + t;
        int dst[4];
#pragma unroll
        for (int j = 0; j < 4; j++) {
            int e = base + j * 256;
            if (e < E_TOT) dst[j] = (e < N_EDGES) ? ei[N_EDGES + e] : (e - N_EDGES);
            else dst[j] = -1;
        }
#pragma unroll
        for (int j = 0; j < 4; j++)
            if (dst[j] >= 0) atomicAdd(&g_deg[dst[j]], 1);
    } else if (b == 333) {
        if (t >= 32 && t < 96) {
            int g = t - 32;
            int lo = 0, hi = N_NODES;
            while (lo < hi) { int m = (lo + hi) >> 1; if (batch[m] < g) lo = m + 1; else hi = m; }
            int s = lo;
            lo = 0; hi = N_NODES;
            int g1 = g + 1;
            while (lo < hi) { int m = (lo + hi) >> 1; if (batch[m] < g1) lo = m + 1; else hi = m; }
            g_cnt[g] = lo - s;
        }
    } else if (b < 342) {
        int warp = (b - 334) * 8 + (t >> 5);
        int lane = t & 31;
        float s = 0.f, d = 0.f;
        for (int c = lane; c < 512; c += 32) {
            float w = W2[warp * 512 + c];
            s += w * as2[c];
            d += w * ad2[c];
        }
        for (int off = 16; off; off >>= 1) {
            s += __shfl_down_sync(0xffffffffu, s, off);
            d += __shfl_down_sync(0xffffffffu, d, off);
        }
        if (lane == 0) { ((float*)g_va4)[warp] = s; ((float*)g_vd4)[warp] = d; }
    } else if (b < 470) {
        int idx = (b - 342) * 256 + t;           // 128*256 == 32768 exactly
        g_pool[idx] = 0.f;
    } else {
        int i = (b - 470) * 256 + t;             // 64*256 == 16384 exactly
        int n = i >> 5, kp = i & 31;
        float w0 = W2[(2 * kp) * 512 + n];
        float w1 = W2[(2 * kp + 1) * 512 + n];
        __nv_bfloat16 h0 = __float2bfloat16(w0), h1 = __float2bfloat16(w1);
        float l0 = w0 - __bfloat162float(h0), l1 = w1 - __bfloat162float(h1);
        __nv_bfloat162 hp; hp.x = h0; hp.y = h1;
        __nv_bfloat162 lp; lp.x = __float2bfloat16(l0); lp.y = __float2bfloat16(l1);
        g_w2thi[n * 32 + kp] = hp;
        g_w2tlo[n * 32 + kp] = lp;
    }
}

// ============ K2: block 0 = shuffle-scan; blocks 1..157 = al1+x4 =============
__global__ void __launch_bounds__(1024)
k_scan_al1(const float* __restrict__ x, const float* __restrict__ W1,
           const float* __restrict__ as1, const float* __restrict__ ad1) {
    int b = blockIdx.x, t = threadIdx.x;
    if (b == 0) {
        __shared__ int sw[32];
        int lane = t & 31, w = t >> 5;
        int v[20];
#pragma unroll
        for (int k = 0; k < 20; k++) {
            int i = k * 1024 + t;
            v[k] = (i < N_NODES) ? g_deg[i] : 0;
        }
        int running = 0;
#pragma unroll
        for (int k = 0; k < 20; k++) {
            int s = v[k];
#pragma unroll
            for (int off = 1; off < 32; off <<= 1) {
                int n = __shfl_up_sync(0xffffffffu, s, off);
                if (lane >= off) s += n;
            }
            if (lane == 31) sw[w] = s;
            __syncthreads();
            if (w == 0) {
                int p = sw[lane];
#pragma unroll
                for (int off = 1; off < 32; off <<= 1) {
                    int n = __shfl_up_sync(0xffffffffu, p, off);
                    if (lane >= off) p += n;
                }
                sw[lane] = p;
            }
            __syncthreads();
            int ex = running + (w ? sw[w - 1] : 0) + s - v[k];
            int i = k * 1024 + t;
            if (i < N_NODES) { g_rowstart[i] = ex; g_fill[i] = ex; }
            running += sw[31];
            __syncthreads();
        }
        if (t == 0) g_rowstart[N_NODES] = running;
    } else {
        __shared__ float sPs[24], sPd[24];
        if (t < 24) {
            int h = t / 3, d = t % 3;
            float ps = 0.f, pd = 0.f;
            for (int c = 0; c < 8; c++) {
                float w = W1[d * 64 + h * 8 + c];
                ps += w * as1[h * 8 + c];
                pd += w * ad1[h * 8 + c];
            }
            sPs[t] = ps;
            sPd[t] = pd;
        }
        __syncthreads();
        int idx = (b - 1) * 1024 + t;
        if (idx < N_NODES * 8) {
            int n = idx >> 3, h = idx & 7;
            float x0 = x[n * 3], x1 = x[n * 3 + 1], x2 = x[n * 3 + 2];
            g_als1[idx] = x0 * sPs[h * 3] + x1 * sPs[h * 3 + 1] + x2 * sPs[h * 3 + 2];
            g_ald1[idx] = x0 * sPd[h * 3] + x1 * sPd[h * 3 + 1] + x2 * sPd[h * 3 + 2];
            if (h == 0) g_x4[n] = make_float4(x0, x1, x2, 0.f);
        }
    }
}

// ============ K3: scatter, 4 edges per thread ================================
__global__ void k_scatter(const int* __restrict__ ei) {
    int base = blockIdx.x * 1024 + threadIdx.x;
    int src[4], dst[4];
#pragma unroll
    for (int j = 0; j < 4; j++) {
        int e = base + j * 256;
        if (e < E_TOT) {
            if (e < N_EDGES) { src[j] = ei[e]; dst[j] = ei[N_EDGES + e]; }
            else             { src[j] = e - N_EDGES; dst[j] = src[j]; }
        } else dst[j] = -1;
    }
#pragma unroll
    for (int j = 0; j < 4; j++) {
        if (dst[j] >= 0) {
            int pos = atomicAdd(&g_fill[dst[j]], 1);
            g_csr[pos] = src[j];
        }
    }
}

// ============ layer-1 aggregate (R6 v3, measured best) =======================
__global__ void k_agg1(const float* __restrict__ W1, const float* __restrict__ b1) {
    int gidx = blockIdx.x * 256 + threadIdx.x;
    int n = gidx >> 4;
    int l = gidx & 15;
    int h = l >> 1, p = l & 1;
    int s0 = g_rowstart[n], s1 = g_rowstart[n + 1];
    int half0 = (s1 - s0 + 1) >> 1;
    int a = p ? (s0 + half0) : s0;
    int bnd = p ? s1 : (s0 + half0);
    float ald = g_ald1[n * 8 + h];
    float wsum = 0.f, xa0 = 0.f, xa1 = 0.f, xa2 = 0.f;
    int i = a;
    for (; i + 2 <= bnd; i += 2) {
        int src0 = g_csr[i], src1 = g_csr[i + 1];
        float e0 = g_als1[src0 * 8 + h] + ald;
        float e1 = g_als1[src1 * 8 + h] + ald;
        float4 xv0 = g_x4[src0];
        float4 xv1 = g_x4[src1];
        e0 = (e0 > 0.f) ? e0 : 0.2f * e0;
        e1 = (e1 > 0.f) ? e1 : 0.2f * e1;
        float w0 = __expf(e0), w1 = __expf(e1);
        wsum += w0 + w1;
        xa0 += w0 * xv0.x + w1 * xv1.x;
        xa1 += w0 * xv0.y + w1 * xv1.y;
        xa2 += w0 * xv0.z + w1 * xv1.z;
    }
    if (i < bnd) {
        int src = g_csr[i];
        float e = g_als1[src * 8 + h] + ald;
        float4 xv = g_x4[src];
        e = (e > 0.f) ? e : 0.2f * e;
        float w = __expf(e);
        wsum += w;
        xa0 += w * xv.x; xa1 += w * xv.y; xa2 += w * xv.z;
    }
    wsum += __shfl_xor_sync(0xffffffffu, wsum, 1);
    xa0  += __shfl_xor_sync(0xffffffffu, xa0, 1);
    xa1  += __shfl_xor_sync(0xffffffffu, xa1, 1);
    xa2  += __shfl_xor_sync(0xffffffffu, xa2, 1);
    float inv = 1.f / wsum;
    xa0 *= inv; xa1 *= inv; xa2 *= inv;
    const float4 w0v = *(const float4*)&W1[4 * l];
    const float4 w1v = *(const float4*)&W1[64 + 4 * l];
    const float4 w2v = *(const float4*)&W1[128 + 4 * l];
    const float4 bv  = *(const float4*)&b1[4 * l];
    float4 o;
    o.x = xa0 * w0v.x + xa1 * w1v.x + xa2 * w2v.x + bv.x;
    o.y = xa0 * w0v.y + xa1 * w1v.y + xa2 * w2v.y + bv.y;
    o.z = xa0 * w0v.z + xa1 * w1v.z + xa2 * w2v.z + bv.z;
    o.w = xa0 * w0v.w + xa1 * w1v.w + xa2 * w2v.w + bv.w;
    o.x = (o.x > 0.f) ? o.x : (__expf(o.x) - 1.f);
    o.y = (o.y > 0.f) ? o.y : (__expf(o.y) - 1.f);
    o.z = (o.z > 0.f) ? o.z : (__expf(o.z) - 1.f);
    o.w = (o.w > 0.f) ? o.w : (__expf(o.w) - 1.f);
    g_o14[n * 16 + l] = o;
    float4 va = g_va4[l], vd = g_vd4[l];
    float ps2 = o.x * va.x + o.y * va.y + o.z * va.z + o.w * va.w;
    float pd2 = o.x * vd.x + o.y * vd.y + o.z * vd.z + o.w * vd.w;
#pragma unroll
    for (int off = 8; off; off >>= 1) {
        ps2 += __shfl_down_sync(0xffffffffu, ps2, off);
        pd2 += __shfl_down_sync(0xffffffffu, pd2, off);
    }
    if (l == 0) { g_als2[n] = ps2; g_ald2[n] = pd2; }
}

// ============ layer-2 aggregate: warp-per-node; emits bf16 hi/lo =============
__global__ void __launch_bounds__(256)
k_agg2() {
    int wid = threadIdx.x >> 5, lane = threadIdx.x & 31;
    int n = blockIdx.x * 8 + wid;
    int q = lane & 15, r = lane >> 4;
    int s0 = g_rowstart[n], s1 = g_rowstart[n + 1];
    float ald = g_ald2[n];
    float wsum = 0.f;
    float4 acc = make_float4(0.f, 0.f, 0.f, 0.f);
    for (int base = s0; base < s1; base += 32) {
        int i = base + lane;
        float w = 0.f;
        int src = 0;
        if (i < s1) {
            src = g_csr[i];
            float e = g_als2[src] + ald;
            e = (e > 0.f) ? e : 0.2f * e;
            w = __expf(e);
        }
        wsum += w;
        int m = (s1 - base < 32) ? (s1 - base) : 32;
        for (int j0 = 0; j0 < m; j0 += 2) {
            int jj = j0 + r;
            float wj = __shfl_sync(0xffffffffu, w, jj & 31);
            int   sj = __shfl_sync(0xffffffffu, src, jj & 31);
            if (jj < m) {
                float4 v = g_o14[sj * 16 + q];
                acc.x += wj * v.x; acc.y += wj * v.y;
                acc.z += wj * v.z; acc.w += wj * v.w;
            }
        }
    }
#pragma unroll
    for (int off = 16; off; off >>= 1)
        wsum += __shfl_xor_sync(0xffffffffu, wsum, off);
    acc.x += __shfl_xor_sync(0xffffffffu, acc.x, 16);
    acc.y += __shfl_xor_sync(0xffffffffu, acc.y, 16);
    acc.z += __shfl_xor_sync(0xffffffffu, acc.z, 16);
    acc.w += __shfl_xor_sync(0xffffffffu, acc.w, 16);
    if (r == 0) {
        float inv = 1.f / wsum;
        acc.x *= inv; acc.y *= inv; acc.z *= inv; acc.w *= inv;
        __nv_bfloat16 hx = __float2bfloat16(acc.x), hy = __float2bfloat16(acc.y);
        __nv_bfloat16 hz = __float2bfloat16(acc.z), hw = __float2bfloat16(acc.w);
        __nv_bfloat162 h01; h01.x = hx; h01.y = hy;
        __nv_bfloat162 h23; h23.x = hz; h23.y = hw;
        __nv_bfloat162 l01, l23;
        l01.x = __float2bfloat16(acc.x - __bfloat162float(hx));
        l01.y = __float2bfloat16(acc.y - __bfloat162float(hy));
        l23.x = __float2bfloat16(acc.z - __bfloat162float(hz));
        l23.y = __float2bfloat16(acc.w - __bfloat162float(hw));
        g_t2hi[n * 32 + q * 2]     = h01;
        g_t2hi[n * 32 + q * 2 + 1] = h23;
        g_t2lo[n * 32 + q * 2]     = l01;
        g_t2lo[n * 32 + q * 2 + 1] = l23;
    }
}

// ============ gemm2 HMMA v2: A tile staged in smem (1x per block), dbl-buf ===
// grid 148 x 512; warp owns 32 cols; 1250 tiles of 16 nodes (exact).
#define MMA_BF16(d, A0, A1, A2, A3, B0, B1)                                     \
    asm volatile("mma.sync.aligned.m16n8k16.row.col.f32.bf16.bf16.f32 "         \
                 "{%0,%1,%2,%3}, {%4,%5,%6,%7}, {%8,%9}, {%0,%1,%2,%3};"        \
                 : "+f"((d)[0]), "+f"((d)[1]), "+f"((d)[2]), "+f"((d)[3])       \
                 : "r"(A0), "r"(A1), "r"(A2), "r"(A3), "r"(B0), "r"(B1))
#define APAD 36   // (4g+8ks+tg) mod 32 distinct for all 32 lanes -> conflict-free

__global__ void __launch_bounds__(512, 1)
k_gemm2_hmma(const float* __restrict__ b2, const int* __restrict__ batch) {
    __shared__ float sstage[16 * 16 * 34];            // per-warp 16x34 padded tiles
    __shared__ uint32_t sA[2][2][16 * APAD];          // [buf][hi/lo][node*APAD+word]
    const uint32_t* t2hi = (const uint32_t*)g_t2hi;
    const uint32_t* t2lo = (const uint32_t*)g_t2lo;
    const uint32_t* w2hi = (const uint32_t*)g_w2thi;
    const uint32_t* w2lo = (const uint32_t*)g_w2tlo;
    int tid = threadIdx.x;
    int wid = tid >> 5, lane = tid & 31;
    int g = lane >> 2, tg = lane & 3;
    int cb = wid * 32;
    float b2c = b2[cb + lane];
    float* stg = sstage + wid * (16 * 34);
    int nodeL = tid >> 5, wordL = tid & 31;           // staging role: 1 word/thread

    // resident B-hi fragments
    int bbase[4];
    uint32_t bh[4][4][2];
#pragma unroll
    for (int nt = 0; nt < 4; nt++) {
        int col = cb + nt * 8 + g;
        bbase[nt] = col * 32 + tg;
#pragma unroll
        for (int ks = 0; ks < 4; ks++) {
            bh[nt][ks][0] = w2hi[bbase[nt] + ks * 8];
            bh[nt][ks][1] = w2hi[bbase[nt] + ks * 8 + 4];
        }
    }

    int tile = blockIdx.x;                            // 148 <= 1250: all have work
    sA[0][0][nodeL * APAD + wordL] = t2hi[(tile * 16 + nodeL) * 32 + wordL];
    sA[0][1][nodeL * APAD + wordL] = t2lo[(tile * 16 + nodeL) * 32 + wordL];
    __syncthreads();
    int buf = 0;
    while (true) {
        // fragments from smem (conflict-free with APAD=36)
        uint32_t ah[4][4], al[4][4];
#pragma unroll
        for (int ks = 0; ks < 4; ks++) {
            int i0 = g * APAD + ks * 8 + tg, i1 = (g + 8) * APAD + ks * 8 + tg;
            ah[ks][0] = sA[buf][0][i0];     ah[ks][1] = sA[buf][0][i1];
            ah[ks][2] = sA[buf][0][i0 + 4]; ah[ks][3] = sA[buf][0][i1 + 4];
            al[ks][0] = sA[buf][1][i0];     al[ks][1] = sA[buf][1][i1];
            al[ks][2] = sA[buf][1][i0 + 4]; al[ks][3] = sA[buf][1][i1 + 4];
        }
        int bt = batch[tile * 16 + (lane & 15)];
        // prefetch next tile into other buffer (overlaps MMA + epilogue)
        int next = tile + (int)gridDim.x;
        bool has_next = (next < N_NODES / 16);
        if (has_next) {
            sA[buf ^ 1][0][nodeL * APAD + wordL] = t2hi[(next * 16 + nodeL) * 32 + wordL];
            sA[buf ^ 1][1][nodeL * APAD + wordL] = t2lo[(next * 16 + nodeL) * 32 + wordL];
        }
        float acc[4][4] = {{0.f, 0.f, 0.f, 0.f}, {0.f, 0.f, 0.f, 0.f},
                           {0.f, 0.f, 0.f, 0.f}, {0.f, 0.f, 0.f, 0.f}};
#pragma unroll
        for (int ks = 0; ks < 4; ks++) {
#pragma unroll
            for (int nt = 0; nt < 4; nt++) {
                uint32_t bl0 = w2lo[bbase[nt] + ks * 8];
                uint32_t bl1 = w2lo[bbase[nt] + ks * 8 + 4];
                MMA_BF16(acc[nt], ah[ks][0], ah[ks][1], ah[ks][2], ah[ks][3],
                         bh[nt][ks][0], bh[nt][ks][1]);
                MMA_BF16(acc[nt], ah[ks][0], ah[ks][1], ah[ks][2], ah[ks][3],
                         bl0, bl1);
                MMA_BF16(acc[nt], al[ks][0], al[ks][1], al[ks][2], al[ks][3],
                         bh[nt][ks][0], bh[nt][ks][1]);
            }
        }
        // stage D to per-warp smem, then run-compressed pooling
        __syncwarp();
#pragma unroll
        for (int nt = 0; nt < 4; nt++) {
            int colb = nt * 8 + 2 * tg;
            stg[g * 34 + colb]           = acc[nt][0];
            stg[g * 34 + colb + 1]       = acc[nt][1];
            stg[(g + 8) * 34 + colb]     = acc[nt][2];
            stg[(g + 8) * 34 + colb + 1] = acc[nt][3];
        }
        __syncwarp();
        int bprev = -1;
        float run = 0.f;
#pragma unroll
        for (int r = 0; r < 16; r++) {
            float o = stg[r * 34 + lane] + b2c;
            o = (o > 0.f) ? o : (__expf(o) - 1.f);   // elu
            int bg = __shfl_sync(0xffffffffu, bt, r);
            if (bg != bprev) {
                if (bprev >= 0) atomicAdd(&g_pool[bprev * 512 + cb + lane], run);
                run = 0.f;
                bprev = bg;
            }
            run += o;
        }
        atomicAdd(&g_pool[bprev * 512 + cb + lane], run);
        if (!has_next) break;
        __syncthreads();                              // buffer handoff
        buf ^= 1;
        tile = next;
    }
}

// ============ final: block = 8-col slice x all graphs; + deg-zero tail =======
__global__ void k_final(const float* __restrict__ Wo, const float* __restrict__ bo,
                        float* __restrict__ out) {
    int b = blockIdx.x;
    if (b < 64) {
        __shared__ float sP[64 * SPS];
        __shared__ float sW[64 * 8];
        __shared__ float sInv[64];
        int tid = threadIdx.x;           // 512
        int g = tid >> 3, j = tid & 7;
        int c = b * 8 + j;
        if (tid < 64) sInv[tid] = 1.f / fmaxf((float)g_cnt[tid], 1.f);
        __syncthreads();
        int kk0 = (tid & 7) * 8;
        float invg = sInv[g];
        float acc = 0.f;
#pragma unroll 1
        for (int kt = 0; kt < 8; kt++) {
            float4 p0 = *(const float4*)&g_pool[g * 512 + kt * 64 + kk0];
            float4 p1 = *(const float4*)&g_pool[g * 512 + kt * 64 + kk0 + 4];
            p0.x *= invg; p0.y *= invg; p0.z *= invg; p0.w *= invg;
            p1.x *= invg; p1.y *= invg; p1.z *= invg; p1.w *= invg;
            *(float4*)&sP[g * SPS + kk0]     = p0;
            *(float4*)&sP[g * SPS + kk0 + 4] = p1;
            sW[tid] = Wo[(kt * 64 + g) * 512 + c];
            __syncthreads();
#pragma unroll 8
            for (int kk = 0; kk < 64; kk++)
                acc += sP[g * SPS + kk] * sW[kk * 8 + j];
            __syncthreads();
        }
        out[g * 512 + c] = acc + bo[c];
    } else {
        int i = (b - 64) * 512 + threadIdx.x;
        if (i < N_NODES) g_deg[i] = 0;
    }
}

// ---------------- launch -------------------------------------------------------
extern "C" void kernel_launch(void* const* d_in, const int* in_sizes, int n_in,
                              void* d_out, int out_size) {
    const float* x     = (const float*)d_in[0];
    const int*   ei    = (const int*)d_in[1];     // int32 (JAX x64 disabled)
    const int*   batch = (const int*)d_in[2];     // int32
    const float* W1    = (const float*)d_in[3];
    const float* as1   = (const float*)d_in[4];
    const float* ad1   = (const float*)d_in[5];
    const float* b1    = (const float*)d_in[6];
    const float* W2    = (const float*)d_in[7];
    const float* as2   = (const float*)d_in[8];
    const float* ad2   = (const float*)d_in[9];
    const float* b2    = (const float*)d_in[10];
    const float* Wo    = (const float*)d_in[11];
    const float* bo    = (const float*)d_in[12];
    float* out = (float*)d_out;

    k_hist_setup<<<534, 256>>>(ei, W2, as2, ad2, batch);
    k_scan_al1<<<158, 1024>>>(x, W1, as1, ad1);
    k_scatter<<<(E_TOT + 1023) / 1024, 256>>>(ei);
    k_agg1<<<(N_NODES * 16) / 256, 256>>>(W1, b1);
    k_agg2<<<N_NODES / 8, 256>>>();
    k_gemm2_hmma<<<148, 512>>>(b2, batch);
    k_final<<<64 + (N_NODES + 511) / 512, 512>>>(Wo, bo, out);
}

// round 14
// speedup vs baseline: 1.2544x; 1.1568x over previous
#include <cuda_runtime.h>
#include <cuda_bf16.h>
#include <cstdint>

#define N_NODES 20000
#define N_EDGES 320000
#define E_TOT   (N_EDGES + N_NODES)
#define N_GRAPHS 64
#define CAP 96                 // bucket capacity; in-deg = Poisson(16)+1, P(>=95) ~ 1e-50
#define SPS 68

// ---------------- scratch (device globals; no allocation allowed) ----------
// INVARIANT: g_fill is zero at kernel_launch entry (zero at module load;
// re-zeroed by the tail of k_final). g_pool zeroed by k_setup.
__device__ float  g_als1[N_NODES * 8];
__device__ float  g_ald1[N_NODES * 8];
__device__ float4 g_x4[N_NODES];
__device__ float4 g_o14[N_NODES * 16];
__device__ float  g_als2[N_NODES];
__device__ float  g_ald2[N_NODES];
__device__ float4 g_va4[16];
__device__ float4 g_vd4[16];
__device__ __align__(16) __nv_bfloat162 g_t2hi[N_NODES * 32];   // [node][64 k] hi
__device__ __align__(16) __nv_bfloat162 g_t2lo[N_NODES * 32];   // lo
__device__ __align__(16) __nv_bfloat162 g_w2thi[512 * 32];      // W2^T [col][64 k] hi
__device__ __align__(16) __nv_bfloat162 g_w2tlo[512 * 32];      // lo
__device__ int    g_fill[N_NODES];        // per-node in-degree counter (bucket fill)
__device__ int    g_csr[N_NODES * CAP];   // bucketed adjacency (src lists by dst)
__device__ float  g_pool[N_GRAPHS * 512];
__device__ int    g_cnt[N_GRAPHS];

// ============ K1: scatter + al1 + va + cnt + pool-zero + W2 split (fused) ====
// blocks [0,333)      : bucket scatter, 4 edges/thread
// block  333          : per-graph counts via binary search
// blocks [334,342)    : va/vd (64 warps)
// blocks [342,470)    : zero g_pool
// blocks [470,534)    : W2^T bf16 hi/lo split
// blocks [534,1159)   : al1 + x4 (160000 items, 625*256 exact)
__global__ void k_setup(const int* __restrict__ ei, const float* __restrict__ x,
                        const float* __restrict__ W1, const float* __restrict__ as1,
                        const float* __restrict__ ad1, const float* __restrict__ W2,
                        const float* __restrict__ as2, const float* __restrict__ ad2,
                        const int* __restrict__ batch) {
    int b = blockIdx.x, t = threadIdx.x;
    if (b < 333) {
        int base = b * 1024 + t;
        int src[4], dst[4];
#pragma unroll
        for (int j = 0; j < 4; j++) {
            int e = base + j * 256;
            if (e < E_TOT) {
                if (e < N_EDGES) { src[j] = ei[e]; dst[j] = ei[N_EDGES + e]; }
                else             { src[j] = e - N_EDGES; dst[j] = src[j]; }
            } else dst[j] = -1;
        }
#pragma unroll
        for (int j = 0; j < 4; j++) {
            if (dst[j] >= 0) {
                int pos = atomicAdd(&g_fill[dst[j]], 1);
                if (pos < CAP) g_csr[dst[j] * CAP + pos] = src[j];
            }
        }
    } else if (b == 333) {
        if (t >= 32 && t < 96) {
            int g = t - 32;
            int lo = 0, hi = N_NODES;
            while (lo < hi) { int m = (lo + hi) >> 1; if (batch[m] < g) lo = m + 1; else hi = m; }
            int s = lo;
            lo = 0; hi = N_NODES;
            int g1 = g + 1;
            while (lo < hi) { int m = (lo + hi) >> 1; if (batch[m] < g1) lo = m + 1; else hi = m; }
            g_cnt[g] = lo - s;
        }
    } else if (b < 342) {
        int warp = (b - 334) * 8 + (t >> 5);     // 0..63
        int lane = t & 31;
        float s = 0.f, d = 0.f;
        for (int c = lane; c < 512; c += 32) {
            float w = W2[warp * 512 + c];
            s += w * as2[c];
            d += w * ad2[c];
        }
        for (int off = 16; off; off >>= 1) {
            s += __shfl_down_sync(0xffffffffu, s, off);
            d += __shfl_down_sync(0xffffffffu, d, off);
        }
        if (lane == 0) { ((float*)g_va4)[warp] = s; ((float*)g_vd4)[warp] = d; }
    } else if (b < 470) {
        int idx = (b - 342) * 256 + t;           // 128*256 == 32768 exactly
        g_pool[idx] = 0.f;
    } else if (b < 534) {
        int i = (b - 470) * 256 + t;             // 64*256 == 16384 exactly
        int n = i >> 5, kp = i & 31;
        float w0 = W2[(2 * kp) * 512 + n];
        float w1 = W2[(2 * kp + 1) * 512 + n];
        __nv_bfloat16 h0 = __float2bfloat16(w0), h1 = __float2bfloat16(w1);
        float l0 = w0 - __bfloat162float(h0), l1 = w1 - __bfloat162float(h1);
        __nv_bfloat162 hp; hp.x = h0; hp.y = h1;
        __nv_bfloat162 lp; lp.x = __float2bfloat16(l0); lp.y = __float2bfloat16(l1);
        g_w2thi[n * 32 + kp] = hp;
        g_w2tlo[n * 32 + kp] = lp;
    } else {
        __shared__ float sPs[24], sPd[24];
        if (t < 24) {
            int h = t / 3, d = t % 3;
            float ps = 0.f, pd = 0.f;
            for (int c = 0; c < 8; c++) {
                float w = W1[d * 64 + h * 8 + c];
                ps += w * as1[h * 8 + c];
                pd += w * ad1[h * 8 + c];
            }
            sPs[t] = ps;
            sPd[t] = pd;
        }
        __syncthreads();
        int idx = (b - 534) * 256 + t;           // 625*256 == 160000 exactly
        int n = idx >> 3, h = idx & 7;
        float x0 = x[n * 3], x1 = x[n * 3 + 1], x2 = x[n * 3 + 2];
        g_als1[idx] = x0 * sPs[h * 3] + x1 * sPs[h * 3 + 1] + x2 * sPs[h * 3 + 2];
        g_ald1[idx] = x0 * sPd[h * 3] + x1 * sPd[h * 3 + 1] + x2 * sPd[h * 3 + 2];
        if (h == 0) g_x4[n] = make_float4(x0, x1, x2, 0.f);
    }
}

// ============ layer-1 aggregate (R6 v3, bucket-CSR addressing) ===============
__global__ void k_agg1(const float* __restrict__ W1, const float* __restrict__ b1) {
    int gidx = blockIdx.x * 256 + threadIdx.x;    // exactly N_NODES*16 threads
    int n = gidx >> 4;
    int l = gidx & 15;          // lane-in-node
    int h = l >> 1, p = l & 1;  // head, half
    int s0 = n * CAP;
    int s1 = s0 + g_fill[n];
    int half0 = (s1 - s0 + 1) >> 1;
    int a = p ? (s0 + half0) : s0;
    int bnd = p ? s1 : (s0 + half0);
    float ald = g_ald1[n * 8 + h];
    float wsum = 0.f, xa0 = 0.f, xa1 = 0.f, xa2 = 0.f;
    int i = a;
    for (; i + 2 <= bnd; i += 2) {
        int src0 = g_csr[i], src1 = g_csr[i + 1];
        float e0 = g_als1[src0 * 8 + h] + ald;
        float e1 = g_als1[src1 * 8 + h] + ald;
        float4 xv0 = g_x4[src0];
        float4 xv1 = g_x4[src1];
        e0 = (e0 > 0.f) ? e0 : 0.2f * e0;
        e1 = (e1 > 0.f) ? e1 : 0.2f * e1;
        float w0 = __expf(e0), w1 = __expf(e1);
        wsum += w0 + w1;
        xa0 += w0 * xv0.x + w1 * xv1.x;
        xa1 += w0 * xv0.y + w1 * xv1.y;
        xa2 += w0 * xv0.z + w1 * xv1.z;
    }
    if (i < bnd) {
        int src = g_csr[i];
        float e = g_als1[src * 8 + h] + ald;
        float4 xv = g_x4[src];
        e = (e > 0.f) ? e : 0.2f * e;
        float w = __expf(e);
        wsum += w;
        xa0 += w * xv.x; xa1 += w * xv.y; xa2 += w * xv.z;
    }
    wsum += __shfl_xor_sync(0xffffffffu, wsum, 1);
    xa0  += __shfl_xor_sync(0xffffffffu, xa0, 1);
    xa1  += __shfl_xor_sync(0xffffffffu, xa1, 1);
    xa2  += __shfl_xor_sync(0xffffffffu, xa2, 1);
    float inv = 1.f / wsum;
    xa0 *= inv; xa1 *= inv; xa2 *= inv;
    const float4 w0v = *(const float4*)&W1[4 * l];
    const float4 w1v = *(const float4*)&W1[64 + 4 * l];
    const float4 w2v = *(const float4*)&W1[128 + 4 * l];
    const float4 bv  = *(const float4*)&b1[4 * l];
    float4 o;
    o.x = xa0 * w0v.x + xa1 * w1v.x + xa2 * w2v.x + bv.x;
    o.y = xa0 * w0v.y + xa1 * w1v.y + xa2 * w2v.y + bv.y;
    o.z = xa0 * w0v.z + xa1 * w1v.z + xa2 * w2v.z + bv.z;
    o.w = xa0 * w0v.w + xa1 * w1v.w + xa2 * w2v.w + bv.w;
    o.x = (o.x > 0.f) ? o.x : (__expf(o.x) - 1.f);
    o.y = (o.y > 0.f) ? o.y : (__expf(o.y) - 1.f);
    o.z = (o.z > 0.f) ? o.z : (__expf(o.z) - 1.f);
    o.w = (o.w > 0.f) ? o.w : (__expf(o.w) - 1.f);
    g_o14[n * 16 + l] = o;
    float4 va = g_va4[l], vd = g_vd4[l];
    float ps2 = o.x * va.x + o.y * va.y + o.z * va.z + o.w * va.w;
    float pd2 = o.x * vd.x + o.y * vd.y + o.z * vd.z + o.w * vd.w;
#pragma unroll
    for (int off = 8; off; off >>= 1) {
        ps2 += __shfl_down_sync(0xffffffffu, ps2, off);
        pd2 += __shfl_down_sync(0xffffffffu, pd2, off);
    }
    if (l == 0) { g_als2[n] = ps2; g_ald2[n] = pd2; }
}

// ============ layer-2 aggregate: warp-per-node; emits bf16 hi/lo =============
__global__ void __launch_bounds__(256)
k_agg2() {
    int wid = threadIdx.x >> 5, lane = threadIdx.x & 31;
    int n = blockIdx.x * 8 + wid;                 // 2500*8 == 20000 exactly
    int q = lane & 15, r = lane >> 4;
    int s0 = n * CAP;
    int s1 = s0 + g_fill[n];
    float ald = g_ald2[n];
    float wsum = 0.f;
    float4 acc = make_float4(0.f, 0.f, 0.f, 0.f);
    for (int base = s0; base < s1; base += 32) {
        int i = base + lane;
        float w = 0.f;
        int src = 0;
        if (i < s1) {
            src = g_csr[i];
            float e = g_als2[src] + ald;
            e = (e > 0.f) ? e : 0.2f * e;
            w = __expf(e);
        }
        wsum += w;
        int m = (s1 - base < 32) ? (s1 - base) : 32;
        for (int j0 = 0; j0 < m; j0 += 2) {
            int jj = j0 + r;
            float wj = __shfl_sync(0xffffffffu, w, jj & 31);
            int   sj = __shfl_sync(0xffffffffu, src, jj & 31);
            if (jj < m) {
                float4 v = g_o14[sj * 16 + q];
                acc.x += wj * v.x; acc.y += wj * v.y;
                acc.z += wj * v.z; acc.w += wj * v.w;
            }
        }
    }
#pragma unroll
    for (int off = 16; off; off >>= 1)
        wsum += __shfl_xor_sync(0xffffffffu, wsum, off);
    acc.x += __shfl_xor_sync(0xffffffffu, acc.x, 16);
    acc.y += __shfl_xor_sync(0xffffffffu, acc.y, 16);
    acc.z += __shfl_xor_sync(0xffffffffu, acc.z, 16);
    acc.w += __shfl_xor_sync(0xffffffffu, acc.w, 16);
    if (r == 0) {
        float inv = 1.f / wsum;
        acc.x *= inv; acc.y *= inv; acc.z *= inv; acc.w *= inv;
        __nv_bfloat16 hx = __float2bfloat16(acc.x), hy = __float2bfloat16(acc.y);
        __nv_bfloat16 hz = __float2bfloat16(acc.z), hw = __float2bfloat16(acc.w);
        __nv_bfloat162 h01; h01.x = hx; h01.y = hy;
        __nv_bfloat162 h23; h23.x = hz; h23.y = hw;
        __nv_bfloat162 l01, l23;
        l01.x = __float2bfloat16(acc.x - __bfloat162float(hx));
        l01.y = __float2bfloat16(acc.y - __bfloat162float(hy));
        l23.x = __float2bfloat16(acc.z - __bfloat162float(hz));
        l23.y = __float2bfloat16(acc.w - __bfloat162float(hw));
        g_t2hi[n * 32 + q * 2]     = h01;
        g_t2hi[n * 32 + q * 2 + 1] = h23;
        g_t2lo[n * 32 + q * 2]     = l01;
        g_t2lo[n * 32 + q * 2 + 1] = l23;
    }
}

// ============ gemm2 HMMA (R13: A staged in smem, double-buffered) ============
#define MMA_BF16(d, A0, A1, A2, A3, B0, B1)                                     \
    asm volatile("mma.sync.aligned.m16n8k16.row.col.f32.bf16.bf16.f32 "         \
                 "{%0,%1,%2,%3}, {%4,%5,%6,%7}, {%8,%9}, {%0,%1,%2,%3};"        \
                 : "+f"((d)[0]), "+f"((d)[1]), "+f"((d)[2]), "+f"((d)[3])       \
                 : "r"(A0), "r"(A1), "r"(A2), "r"(A3), "r"(B0), "r"(B1))
#define APAD 36

__global__ void __launch_bounds__(512, 1)
k_gemm2_hmma(const float* __restrict__ b2, const int* __restrict__ batch) {
    __shared__ float sstage[16 * 16 * 34];
    __shared__ uint32_t sA[2][2][16 * APAD];
    const uint32_t* t2hi = (const uint32_t*)g_t2hi;
    const uint32_t* t2lo = (const uint32_t*)g_t2lo;
    const uint32_t* w2hi = (const uint32_t*)g_w2thi;
    const uint32_t* w2lo = (const uint32_t*)g_w2tlo;
    int tid = threadIdx.x;
    int wid = tid >> 5, lane = tid & 31;
    int g = lane >> 2, tg = lane & 3;
    int cb = wid * 32;
    float b2c = b2[cb + lane];
    float* stg = sstage + wid * (16 * 34);
    int nodeL = tid >> 5, wordL = tid & 31;

    int bbase[4];
    uint32_t bh[4][4][2];
#pragma unroll
    for (int nt = 0; nt < 4; nt++) {
        int col = cb + nt * 8 + g;
        bbase[nt] = col * 32 + tg;
#pragma unroll
        for (int ks = 0; ks < 4; ks++) {
            bh[nt][ks][0] = w2hi[bbase[nt] + ks * 8];
            bh[nt][ks][1] = w2hi[bbase[nt] + ks * 8 + 4];
        }
    }

    int tile = blockIdx.x;
    sA[0][0][nodeL * APAD + wordL] = t2hi[(tile * 16 + nodeL) * 32 + wordL];
    sA[0][1][nodeL * APAD + wordL] = t2lo[(tile * 16 + nodeL) * 32 + wordL];
    __syncthreads();
    int buf = 0;
    while (true) {
        uint32_t ah[4][4], al[4][4];
#pragma unroll
        for (int ks = 0; ks < 4; ks++) {
            int i0 = g * APAD + ks * 8 + tg, i1 = (g + 8) * APAD + ks * 8 + tg;
            ah[ks][0] = sA[buf][0][i0];     ah[ks][1] = sA[buf][0][i1];
            ah[ks][2] = sA[buf][0][i0 + 4]; ah[ks][3] = sA[buf][0][i1 + 4];
            al[ks][0] = sA[buf][1][i0];     al[ks][1] = sA[buf][1][i1];
            al[ks][2] = sA[buf][1][i0 + 4]; al[ks][3] = sA[buf][1][i1 + 4];
        }
        int bt = batch[tile * 16 + (lane & 15)];
        int next = tile + (int)gridDim.x;
        bool has_next = (next < N_NODES / 16);
        if (has_next) {
            sA[buf ^ 1][0][nodeL * APAD + wordL] = t2hi[(next * 16 + nodeL) * 32 + wordL];
            sA[buf ^ 1][1][nodeL * APAD + wordL] = t2lo[(next * 16 + nodeL) * 32 + wordL];
        }
        float acc[4][4] = {{0.f, 0.f, 0.f, 0.f}, {0.f, 0.f, 0.f, 0.f},
                           {0.f, 0.f, 0.f, 0.f}, {0.f, 0.f, 0.f, 0.f}};
#pragma unroll
        for (int ks = 0; ks < 4; ks++) {
#pragma unroll
            for (int nt = 0; nt < 4; nt++) {
                uint32_t bl0 = w2lo[bbase[nt] + ks * 8];
                uint32_t bl1 = w2lo[bbase[nt] + ks * 8 + 4];
                MMA_BF16(acc[nt], ah[ks][0], ah[ks][1], ah[ks][2], ah[ks][3],
                         bh[nt][ks][0], bh[nt][ks][1]);
                MMA_BF16(acc[nt], ah[ks][0], ah[ks][1], ah[ks][2], ah[ks][3],
                         bl0, bl1);
                MMA_BF16(acc[nt], al[ks][0], al[ks][1], al[ks][2], al[ks][3],
                         bh[nt][ks][0], bh[nt][ks][1]);
            }
        }
        __syncwarp();
#pragma unroll
        for (int nt = 0; nt < 4; nt++) {
            int colb = nt * 8 + 2 * tg;
            stg[g * 34 + colb]           = acc[nt][0];
            stg[g * 34 + colb + 1]       = acc[nt][1];
            stg[(g + 8) * 34 + colb]     = acc[nt][2];
            stg[(g + 8) * 34 + colb + 1] = acc[nt][3];
        }
        __syncwarp();
        int bprev = -1;
        float run = 0.f;
#pragma unroll
        for (int r = 0; r < 16; r++) {
            float o = stg[r * 34 + lane] + b2c;
            o = (o > 0.f) ? o : (__expf(o) - 1.f);   // elu
            int bg = __shfl_sync(0xffffffffu, bt, r);
            if (bg != bprev) {
                if (bprev >= 0) atomicAdd(&g_pool[bprev * 512 + cb + lane], run);
                run = 0.f;
                bprev = bg;
            }
            run += o;
        }
        atomicAdd(&g_pool[bprev * 512 + cb + lane], run);
        if (!has_next) break;
        __syncthreads();
        buf ^= 1;
        tile = next;
    }
}

// ============ final: block = 8-col slice x all graphs; + fill-zero tail ======
__global__ void k_final(const float* __restrict__ Wo, const float* __restrict__ bo,
                        float* __restrict__ out) {
    int b = blockIdx.x;
    if (b < 64) {
        __shared__ float sP[64 * SPS];
        __shared__ float sW[64 * 8];
        __shared__ float sInv[64];
        int tid = threadIdx.x;           // 512
        int g = tid >> 3, j = tid & 7;
        int c = b * 8 + j;
        if (tid < 64) sInv[tid] = 1.f / fmaxf((float)g_cnt[tid], 1.f);
        __syncthreads();
        int kk0 = (tid & 7) * 8;
        float invg = sInv[g];
        float acc = 0.f;
#pragma unroll 1
        for (int kt = 0; kt < 8; kt++) {
            float4 p0 = *(const float4*)&g_pool[g * 512 + kt * 64 + kk0];
            float4 p1 = *(const float4*)&g_pool[g * 512 + kt * 64 + kk0 + 4];
            p0.x *= invg; p0.y *= invg; p0.z *= invg; p0.w *= invg;
            p1.x *= invg; p1.y *= invg; p1.z *= invg; p1.w *= invg;
            *(float4*)&sP[g * SPS + kk0]     = p0;
            *(float4*)&sP[g * SPS + kk0 + 4] = p1;
            sW[tid] = Wo[(kt * 64 + g) * 512 + c];
            __syncthreads();
#pragma unroll 8
            for (int kk = 0; kk < 64; kk++)
                acc += sP[g * SPS + kk] * sW[kk * 8 + j];
            __syncthreads();
        }
        out[g * 512 + c] = acc + bo[c];
    } else {
        int i = (b - 64) * 512 + threadIdx.x;
        if (i < N_NODES) g_fill[i] = 0;  // restore invariant for next call
    }
}

// ---------------- launch -------------------------------------------------------
extern "C" void kernel_launch(void* const* d_in, const int* in_sizes, int n_in,
                              void* d_out, int out_size) {
    const float* x     = (const float*)d_in[0];
    const int*   ei    = (const int*)d_in[1];     // int32 (JAX x64 disabled)
    const int*   batch = (const int*)d_in[2];     // int32
    const float* W1    = (const float*)d_in[3];
    const float* as1   = (const float*)d_in[4];
    const float* ad1   = (const float*)d_in[5];
    const float* b1    = (const float*)d_in[6];
    const float* W2    = (const float*)d_in[7];
    const float* as2   = (const float*)d_in[8];
    const float* ad2   = (const float*)d_in[9];
    const float* b2    = (const float*)d_in[10];
    const float* Wo    = (const float*)d_in[11];
    const float* bo    = (const float*)d_in[12];
    float* out = (float*)d_out;

    k_setup<<<1159, 256>>>(ei, x, W1, as1, ad1, W2, as2, ad2, batch);
    k_agg1<<<(N_NODES * 16) / 256, 256>>>(W1, b1);
    k_agg2<<<N_NODES / 8, 256>>>();
    k_gemm2_hmma<<<148, 512>>>(b2, batch);
    k_final<<<64 + (N_NODES + 511) / 512, 512>>>(Wo, bo, out);
}

// round 15
// speedup vs baseline: 1.4961x; 1.1927x over previous
#include <cuda_runtime.h>
#include <cuda_bf16.h>
#include <cstdint>

#define N_NODES 20000
#define N_EDGES 320000
#define E_TOT   (N_EDGES + N_NODES)
#define N_GRAPHS 64
#define CAP 96                 // bucket capacity; in-deg = Poisson(16)+1, P(>=95) ~ 1e-50
#define SPS 68

// ---------------- scratch (device globals; no allocation allowed) ----------
// INVARIANT: g_fill is zero at kernel_launch entry (zero at module load;
// re-zeroed by the tail of k_final). g_pool zeroed by k_setup.
__device__ float  g_als1[N_NODES * 8];
__device__ float  g_ald1[N_NODES * 8];
__device__ float4 g_x4[N_NODES];
__device__ float4 g_o14[N_NODES * 16];
__device__ float  g_als2[N_NODES];
__device__ float  g_ald2[N_NODES];
__device__ float4 g_va4[16];
__device__ float4 g_vd4[16];
__device__ __align__(16) __nv_bfloat162 g_t2hi[N_NODES * 32];   // [node][64 k] hi
__device__ __align__(16) __nv_bfloat162 g_t2lo[N_NODES * 32];   // lo
__device__ __align__(16) __nv_bfloat162 g_w2thi[512 * 32];      // W2^T [col][64 k] hi
__device__ __align__(16) __nv_bfloat162 g_w2tlo[512 * 32];      // lo
__device__ int    g_fill[N_NODES];        // per-node in-degree counter (bucket fill)
__device__ int    g_csr[N_NODES * CAP];   // bucketed adjacency (src lists by dst)
__device__ float  g_pool[N_GRAPHS * 512];
__device__ int    g_cnt[N_GRAPHS];

// ============ K1: scatter + al1 + va + cnt + pool-zero + W2 split (fused) ====
__global__ void k_setup(const int* __restrict__ ei, const float* __restrict__ x,
                        const float* __restrict__ W1, const float* __restrict__ as1,
                        const float* __restrict__ ad1, const float* __restrict__ W2,
                        const float* __restrict__ as2, const float* __restrict__ ad2,
                        const int* __restrict__ batch) {
    int b = blockIdx.x, t = threadIdx.x;
    if (b < 333) {
        int base = b * 1024 + t;
        int src[4], dst[4];
#pragma unroll
        for (int j = 0; j < 4; j++) {
            int e = base + j * 256;
            if (e < E_TOT) {
                if (e < N_EDGES) { src[j] = ei[e]; dst[j] = ei[N_EDGES + e]; }
                else             { src[j] = e - N_EDGES; dst[j] = src[j]; }
            } else dst[j] = -1;
        }
#pragma unroll
        for (int j = 0; j < 4; j++) {
            if (dst[j] >= 0) {
                int pos = atomicAdd(&g_fill[dst[j]], 1);
                if (pos < CAP) g_csr[dst[j] * CAP + pos] = src[j];
            }
        }
    } else if (b == 333) {
        if (t >= 32 && t < 96) {
            int g = t - 32;
            int lo = 0, hi = N_NODES;
            while (lo < hi) { int m = (lo + hi) >> 1; if (batch[m] < g) lo = m + 1; else hi = m; }
            int s = lo;
            lo = 0; hi = N_NODES;
            int g1 = g + 1;
            while (lo < hi) { int m = (lo + hi) >> 1; if (batch[m] < g1) lo = m + 1; else hi = m; }
            g_cnt[g] = lo - s;
        }
    } else if (b < 342) {
        int warp = (b - 334) * 8 + (t >> 5);     // 0..63
        int lane = t & 31;
        float s = 0.f, d = 0.f;
        for (int c = lane; c < 512; c += 32) {
            float w = W2[warp * 512 + c];
            s += w * as2[c];
            d += w * ad2[c];
        }
        for (int off = 16; off; off >>= 1) {
            s += __shfl_down_sync(0xffffffffu, s, off);
            d += __shfl_down_sync(0xffffffffu, d, off);
        }
        if (lane == 0) { ((float*)g_va4)[warp] = s; ((float*)g_vd4)[warp] = d; }
    } else if (b < 470) {
        int idx = (b - 342) * 256 + t;           // 128*256 == 32768 exactly
        g_pool[idx] = 0.f;
    } else if (b < 534) {
        int i = (b - 470) * 256 + t;             // 64*256 == 16384 exactly
        int n = i >> 5, kp = i & 31;
        float w0 = W2[(2 * kp) * 512 + n];
        float w1 = W2[(2 * kp + 1) * 512 + n];
        __nv_bfloat16 h0 = __float2bfloat16(w0), h1 = __float2bfloat16(w1);
        float l0 = w0 - __bfloat162float(h0), l1 = w1 - __bfloat162float(h1);
        __nv_bfloat162 hp; hp.x = h0; hp.y = h1;
        __nv_bfloat162 lp; lp.x = __float2bfloat16(l0); lp.y = __float2bfloat16(l1);
        g_w2thi[n * 32 + kp] = hp;
        g_w2tlo[n * 32 + kp] = lp;
    } else {
        __shared__ float sPs[24], sPd[24];
        if (t < 24) {
            int h = t / 3, d = t % 3;
            float ps = 0.f, pd = 0.f;
            for (int c = 0; c < 8; c++) {
                float w = W1[d * 64 + h * 8 + c];
                ps += w * as1[h * 8 + c];
                pd += w * ad1[h * 8 + c];
            }
            sPs[t] = ps;
            sPd[t] = pd;
        }
        __syncthreads();
        int idx = (b - 534) * 256 + t;           // 625*256 == 160000 exactly
        int n = idx >> 3, h = idx & 7;
        float x0 = x[n * 3], x1 = x[n * 3 + 1], x2 = x[n * 3 + 2];
        g_als1[idx] = x0 * sPs[h * 3] + x1 * sPs[h * 3 + 1] + x2 * sPs[h * 3 + 2];
        g_ald1[idx] = x0 * sPd[h * 3] + x1 * sPd[h * 3 + 1] + x2 * sPd[h * 3 + 2];
        if (h == 0) g_x4[n] = make_float4(x0, x1, x2, 0.f);
    }
}

// ============ layer-1 aggregate (R6 v3, bucket-CSR addressing) ===============
__global__ void k_agg1(const float* __restrict__ W1, const float* __restrict__ b1) {
    int gidx = blockIdx.x * 256 + threadIdx.x;    // exactly N_NODES*16 threads
    int n = gidx >> 4;
    int l = gidx & 15;
    int h = l >> 1, p = l & 1;
    int s0 = n * CAP;
    int s1 = s0 + g_fill[n];
    int half0 = (s1 - s0 + 1) >> 1;
    int a = p ? (s0 + half0) : s0;
    int bnd = p ? s1 : (s0 + half0);
    float ald = g_ald1[n * 8 + h];
    float wsum = 0.f, xa0 = 0.f, xa1 = 0.f, xa2 = 0.f;
    int i = a;
    for (; i + 2 <= bnd; i += 2) {
        int src0 = g_csr[i], src1 = g_csr[i + 1];
        float e0 = g_als1[src0 * 8 + h] + ald;
        float e1 = g_als1[src1 * 8 + h] + ald;
        float4 xv0 = g_x4[src0];
        float4 xv1 = g_x4[src1];
        e0 = (e0 > 0.f) ? e0 : 0.2f * e0;
        e1 = (e1 > 0.f) ? e1 : 0.2f * e1;
        float w0 = __expf(e0), w1 = __expf(e1);
        wsum += w0 + w1;
        xa0 += w0 * xv0.x + w1 * xv1.x;
        xa1 += w0 * xv0.y + w1 * xv1.y;
        xa2 += w0 * xv0.z + w1 * xv1.z;
    }
    if (i < bnd) {
        int src = g_csr[i];
        float e = g_als1[src * 8 + h] + ald;
        float4 xv = g_x4[src];
        e = (e > 0.f) ? e : 0.2f * e;
        float w = __expf(e);
        wsum += w;
        xa0 += w * xv.x; xa1 += w * xv.y; xa2 += w * xv.z;
    }
    wsum += __shfl_xor_sync(0xffffffffu, wsum, 1);
    xa0  += __shfl_xor_sync(0xffffffffu, xa0, 1);
    xa1  += __shfl_xor_sync(0xffffffffu, xa1, 1);
    xa2  += __shfl_xor_sync(0xffffffffu, xa2, 1);
    float inv = 1.f / wsum;
    xa0 *= inv; xa1 *= inv; xa2 *= inv;
    const float4 w0v = *(const float4*)&W1[4 * l];
    const float4 w1v = *(const float4*)&W1[64 + 4 * l];
    const float4 w2v = *(const float4*)&W1[128 + 4 * l];
    const float4 bv  = *(const float4*)&b1[4 * l];
    float4 o;
    o.x = xa0 * w0v.x + xa1 * w1v.x + xa2 * w2v.x + bv.x;
    o.y = xa0 * w0v.y + xa1 * w1v.y + xa2 * w2v.y + bv.y;
    o.z = xa0 * w0v.z + xa1 * w1v.z + xa2 * w2v.z + bv.z;
    o.w = xa0 * w0v.w + xa1 * w1v.w + xa2 * w2v.w + bv.w;
    o.x = (o.x > 0.f) ? o.x : (__expf(o.x) - 1.f);
    o.y = (o.y > 0.f) ? o.y : (__expf(o.y) - 1.f);
    o.z = (o.z > 0.f) ? o.z : (__expf(o.z) - 1.f);
    o.w = (o.w > 0.f) ? o.w : (__expf(o.w) - 1.f);
    g_o14[n * 16 + l] = o;
    float4 va = g_va4[l], vd = g_vd4[l];
    float ps2 = o.x * va.x + o.y * va.y + o.z * va.z + o.w * va.w;
    float pd2 = o.x * vd.x + o.y * vd.y + o.z * vd.z + o.w * vd.w;
#pragma unroll
    for (int off = 8; off; off >>= 1) {
        ps2 += __shfl_down_sync(0xffffffffu, ps2, off);
        pd2 += __shfl_down_sync(0xffffffffu, pd2, off);
    }
    if (l == 0) { g_als2[n] = ps2; g_ald2[n] = pd2; }
}

// ============ layer-2 aggregate: warp-per-node; emits bf16 hi/lo =============
__global__ void __launch_bounds__(256)
k_agg2() {
    int wid = threadIdx.x >> 5, lane = threadIdx.x & 31;
    int n = blockIdx.x * 8 + wid;
    int q = lane & 15, r = lane >> 4;
    int s0 = n * CAP;
    int s1 = s0 + g_fill[n];
    float ald = g_ald2[n];
    float wsum = 0.f;
    float4 acc = make_float4(0.f, 0.f, 0.f, 0.f);
    for (int base = s0; base < s1; base += 32) {
        int i = base + lane;
        float w = 0.f;
        int src = 0;
        if (i < s1) {
            src = g_csr[i];
            float e = g_als2[src] + ald;
            e = (e > 0.f) ? e : 0.2f * e;
            w = __expf(e);
        }
        wsum += w;
        int m = (s1 - base < 32) ? (s1 - base) : 32;
        for (int j0 = 0; j0 < m; j0 += 2) {
            int jj = j0 + r;
            float wj = __shfl_sync(0xffffffffu, w, jj & 31);
            int   sj = __shfl_sync(0xffffffffu, src, jj & 31);
            if (jj < m) {
                float4 v = g_o14[sj * 16 + q];
                acc.x += wj * v.x; acc.y += wj * v.y;
                acc.z += wj * v.z; acc.w += wj * v.w;
            }
        }
    }
#pragma unroll
    for (int off = 16; off; off >>= 1)
        wsum += __shfl_xor_sync(0xffffffffu, wsum, off);
    acc.x += __shfl_xor_sync(0xffffffffu, acc.x, 16);
    acc.y += __shfl_xor_sync(0xffffffffu, acc.y, 16);
    acc.z += __shfl_xor_sync(0xffffffffu, acc.z, 16);
    acc.w += __shfl_xor_sync(0xffffffffu, acc.w, 16);
    if (r == 0) {
        float inv = 1.f / wsum;
        acc.x *= inv; acc.y *= inv; acc.z *= inv; acc.w *= inv;
        __nv_bfloat16 hx = __float2bfloat16(acc.x), hy = __float2bfloat16(acc.y);
        __nv_bfloat16 hz = __float2bfloat16(acc.z), hw = __float2bfloat16(acc.w);
        __nv_bfloat162 h01; h01.x = hx; h01.y = hy;
        __nv_bfloat162 h23; h23.x = hz; h23.y = hw;
        __nv_bfloat162 l01, l23;
        l01.x = __float2bfloat16(acc.x - __bfloat162float(hx));
        l01.y = __float2bfloat16(acc.y - __bfloat162float(hy));
        l23.x = __float2bfloat16(acc.z - __bfloat162float(hz));
        l23.y = __float2bfloat16(acc.w - __bfloat162float(hw));
        g_t2hi[n * 32 + q * 2]     = h01;
        g_t2hi[n * 32 + q * 2 + 1] = h23;
        g_t2lo[n * 32 + q * 2]     = l01;
        g_t2lo[n * 32 + q * 2 + 1] = l23;
    }
}

// ============ gemm2 HMMA v3: 256 thr, col-half split, B hi+lo in regs ========
// grid 296 = 148 stripes x 2 col-halves; block = 8 warps; warp owns 32 cols.
#define MMA_BF16(d, A0, A1, A2, A3, B0, B1)                                     \
    asm volatile("mma.sync.aligned.m16n8k16.row.col.f32.bf16.bf16.f32 "         \
                 "{%0,%1,%2,%3}, {%4,%5,%6,%7}, {%8,%9}, {%0,%1,%2,%3};"        \
                 : "+f"((d)[0]), "+f"((d)[1]), "+f"((d)[2]), "+f"((d)[3])       \
                 : "r"(A0), "r"(A1), "r"(A2), "r"(A3), "r"(B0), "r"(B1))
#define APAD 36

__global__ void __launch_bounds__(256, 2)
k_gemm2_hmma(const float* __restrict__ b2, const int* __restrict__ batch) {
    __shared__ float sstage[8 * 16 * 34];
    __shared__ uint32_t sA[2][2][16 * APAD];
    const uint32_t* t2hi = (const uint32_t*)g_t2hi;
    const uint32_t* t2lo = (const uint32_t*)g_t2lo;
    const uint32_t* w2hi = (const uint32_t*)g_w2thi;
    const uint32_t* w2lo = (const uint32_t*)g_w2tlo;
    int tid = threadIdx.x;
    int wid = tid >> 5, lane = tid & 31;
    int g = lane >> 2, tg = lane & 3;
    int colhalf = blockIdx.x & 1;
    int stripe = blockIdx.x >> 1;                 // 0..147
    int cb = colhalf * 256 + wid * 32;
    float b2c = b2[cb + lane];
    float* stg = sstage + wid * (16 * 34);

    // resident B fragments: hi AND lo (loop-invariant)
    uint32_t bh[4][4][2], bl[4][4][2];
#pragma unroll
    for (int nt = 0; nt < 4; nt++) {
        int bbase = (cb + nt * 8 + g) * 32 + tg;
#pragma unroll
        for (int ks = 0; ks < 4; ks++) {
            bh[nt][ks][0] = w2hi[bbase + ks * 8];
            bh[nt][ks][1] = w2hi[bbase + ks * 8 + 4];
            bl[nt][ks][0] = w2lo[bbase + ks * 8];
            bl[nt][ks][1] = w2lo[bbase + ks * 8 + 4];
        }
    }

    int tile = stripe;                            // 148 <= 1250: all have work
#pragma unroll 1
    for (int ch = tid; ch < 512; ch += 256) {     // 2 hi + 2 lo words per thread
        int node = ch >> 5, word = ch & 31;
        sA[0][0][node * APAD + word] = t2hi[(tile * 16 + node) * 32 + word];
        sA[0][1][node * APAD + word] = t2lo[(tile * 16 + node) * 32 + word];
    }
    __syncthreads();
    int buf = 0;
    while (true) {
        int bt = batch[tile * 16 + (lane & 15)];
        int next = tile + 148;
        bool has_next = (next < N_NODES / 16);
        if (has_next) {
#pragma unroll 1
            for (int ch = tid; ch < 512; ch += 256) {
                int node = ch >> 5, word = ch & 31;
                sA[buf ^ 1][0][node * APAD + word] = t2hi[(next * 16 + node) * 32 + word];
                sA[buf ^ 1][1][node * APAD + word] = t2lo[(next * 16 + node) * 32 + word];
            }
        }
        float acc[4][4] = {{0.f, 0.f, 0.f, 0.f}, {0.f, 0.f, 0.f, 0.f},
                           {0.f, 0.f, 0.f, 0.f}, {0.f, 0.f, 0.f, 0.f}};
#pragma unroll
        for (int ks = 0; ks < 4; ks++) {
            // A fragments for this ks only (8 regs live)
            int i0 = g * APAD + ks * 8 + tg, i1 = (g + 8) * APAD + ks * 8 + tg;
            uint32_t ah0 = sA[buf][0][i0],     ah1 = sA[buf][0][i1];
            uint32_t ah2 = sA[buf][0][i0 + 4], ah3 = sA[buf][0][i1 + 4];
            uint32_t al0 = sA[buf][1][i0],     al1 = sA[buf][1][i1];
            uint32_t al2 = sA[buf][1][i0 + 4], al3 = sA[buf][1][i1 + 4];
#pragma unroll
            for (int nt = 0; nt < 4; nt++) {
                MMA_BF16(acc[nt], ah0, ah1, ah2, ah3, bh[nt][ks][0], bh[nt][ks][1]);
                MMA_BF16(acc[nt], ah0, ah1, ah2, ah3, bl[nt][ks][0], bl[nt][ks][1]);
                MMA_BF16(acc[nt], al0, al1, al2, al3, bh[nt][ks][0], bh[nt][ks][1]);
            }
        }
        __syncwarp();
#pragma unroll
        for (int nt = 0; nt < 4; nt++) {
            int colb = nt * 8 + 2 * tg;
            stg[g * 34 + colb]           = acc[nt][0];
            stg[g * 34 + colb + 1]       = acc[nt][1];
            stg[(g + 8) * 34 + colb]     = acc[nt][2];
            stg[(g + 8) * 34 + colb + 1] = acc[nt][3];
        }
        __syncwarp();
        int bprev = -1;
        float run = 0.f;
#pragma unroll
        for (int r = 0; r < 16; r++) {
            float o = stg[r * 34 + lane] + b2c;
            o = (o > 0.f) ? o : (__expf(o) - 1.f);   // elu
            int bg = __shfl_sync(0xffffffffu, bt, r);
            if (bg != bprev) {
                if (bprev >= 0) atomicAdd(&g_pool[bprev * 512 + cb + lane], run);
                run = 0.f;
                bprev = bg;
            }
            run += o;
        }
        atomicAdd(&g_pool[bprev * 512 + cb + lane], run);
        if (!has_next) break;
        __syncthreads();
        buf ^= 1;
        tile = next;
    }
}

// ============ final: block = 8-col slice x all graphs; + fill-zero tail ======
__global__ void k_final(const float* __restrict__ Wo, const float* __restrict__ bo,
                        float* __restrict__ out) {
    int b = blockIdx.x;
    if (b < 64) {
        __shared__ float sP[64 * SPS];
        __shared__ float sW[64 * 8];
        __shared__ float sInv[64];
        int tid = threadIdx.x;           // 512
        int g = tid >> 3, j = tid & 7;
        int c = b * 8 + j;
        if (tid < 64) sInv[tid] = 1.f / fmaxf((float)g_cnt[tid], 1.f);
        __syncthreads();
        int kk0 = (tid & 7) * 8;
        float invg = sInv[g];
        float acc = 0.f;
#pragma unroll 1
        for (int kt = 0; kt < 8; kt++) {
            float4 p0 = *(const float4*)&g_pool[g * 512 + kt * 64 + kk0];
            float4 p1 = *(const float4*)&g_pool[g * 512 + kt * 64 + kk0 + 4];
            p0.x *= invg; p0.y *= invg; p0.z *= invg; p0.w *= invg;
            p1.x *= invg; p1.y *= invg; p1.z *= invg; p1.w *= invg;
            *(float4*)&sP[g * SPS + kk0]     = p0;
            *(float4*)&sP[g * SPS + kk0 + 4] = p1;
            sW[tid] = Wo[(kt * 64 + g) * 512 + c];
            __syncthreads();
#pragma unroll 8
            for (int kk = 0; kk < 64; kk++)
                acc += sP[g * SPS + kk] * sW[kk * 8 + j];
            __syncthreads();
        }
        out[g * 512 + c] = acc + bo[c];
    } else {
        int i = (b - 64) * 512 + threadIdx.x;
        if (i < N_NODES) g_fill[i] = 0;  // restore invariant for next call
    }
}

// ---------------- launch -------------------------------------------------------
extern "C" void kernel_launch(void* const* d_in, const int* in_sizes, int n_in,
                              void* d_out, int out_size) {
    const float* x     = (const float*)d_in[0];
    const int*   ei    = (const int*)d_in[1];     // int32 (JAX x64 disabled)
    const int*   batch = (const int*)d_in[2];     // int32
    const float* W1    = (const float*)d_in[3];
    const float* as1   = (const float*)d_in[4];
    const float* ad1   = (const float*)d_in[5];
    const float* b1    = (const float*)d_in[6];
    const float* W2    = (const float*)d_in[7];
    const float* as2   = (const float*)d_in[8];
    const float* ad2   = (const float*)d_in[9];
    const float* b2    = (const float*)d_in[10];
    const float* Wo    = (const float*)d_in[11];
    const float* bo    = (const float*)d_in[12];
    float* out = (float*)d_out;

    k_setup<<<1159, 256>>>(ei, x, W1, as1, ad1, W2, as2, ad2, batch);
    k_agg1<<<(N_NODES * 16) / 256, 256>>>(W1, b1);
    k_agg2<<<N_NODES / 8, 256>>>();
    k_gemm2_hmma<<<296, 256>>>(b2, batch);
    k_final<<<64 + (N_NODES + 511) / 512, 512>>>(Wo, bo, out);
}